// round 14
// baseline (speedup 1.0000x reference)
#include <cuda_runtime.h>
#include <cuda_bf16.h>
#include <math.h>
#include <stdint.h>

#define NHEADS 8
#define DIMH   64
#define BATCH  4
#define NQ     2048
#define NC     2048
#define DQ     1024
#define DC     768
#define INNER  512
#define MROWS  (BATCH * NQ)   // 8192

#define SCL2E 0.18033688f   // SCALE * log2(e), folded into Q projection

// ---------------------------------------------------------------------------
// Scratch
// ---------------------------------------------------------------------------
__device__ __nv_bfloat16 g_xh[MROWS * DQ];
__device__ __nv_bfloat16 g_xl[MROWS * DQ];
__device__ __nv_bfloat16 g_ch[MROWS * DC];
__device__ __nv_bfloat16 g_cl[MROWS * DC];

__device__ __nv_bfloat16 g_qh[MROWS * INNER];
__device__ __nv_bfloat16 g_ql[MROWS * INNER];
__device__ __nv_bfloat16 g_kh[MROWS * INNER];
__device__ __nv_bfloat16 g_kl[MROWS * INNER];
__device__ __nv_bfloat16 g_vh[MROWS * INNER];
__device__ __nv_bfloat16 g_vl[MROWS * INNER];
__device__ __nv_bfloat16 g_aoh[MROWS * INNER];
__device__ __nv_bfloat16 g_aol[MROWS * INNER];

__device__ __nv_bfloat16 g_wqh[INNER * DQ];
__device__ __nv_bfloat16 g_wql[INNER * DQ];
__device__ __nv_bfloat16 g_wkvh[2 * INNER * DC];
__device__ __nv_bfloat16 g_wkvl[2 * INNER * DC];
__device__ __nv_bfloat16 g_woh[DQ * INNER];
__device__ __nv_bfloat16 g_wol[DQ * INNER];

// ---------------------------------------------------------------------------
// PTX helpers
// ---------------------------------------------------------------------------
__device__ __forceinline__ uint32_t smem_u32(const void* p) {
    uint32_t a;
    asm("{ .reg .u64 t; cvta.to.shared.u64 t, %1; cvt.u32.u64 %0, t; }" : "=r"(a) : "l"(p));
    return a;
}
__device__ __forceinline__ void cpa16(uint32_t dst, const void* src) {
    asm volatile("cp.async.cg.shared.global [%0], [%1], 16;" :: "r"(dst), "l"(src));
}
__device__ __forceinline__ void cpa_commit() { asm volatile("cp.async.commit_group;" ::: "memory"); }
__device__ __forceinline__ void cpa_wait0()  { asm volatile("cp.async.wait_group 0;" ::: "memory"); }
__device__ __forceinline__ void cpa_wait1()  { asm volatile("cp.async.wait_group 1;" ::: "memory"); }
__device__ __forceinline__ void cpa_wait2()  { asm volatile("cp.async.wait_group 2;" ::: "memory"); }

__device__ __forceinline__ float ex2f(float x) {
    float y;
    asm("ex2.approx.f32 %0, %1;" : "=f"(y) : "f"(x));
    return y;
}

__device__ __forceinline__ void ldsm4(uint32_t* r, uint32_t addr) {
    asm volatile("ldmatrix.sync.aligned.m8n8.x4.shared.b16 {%0,%1,%2,%3}, [%4];"
                 : "=r"(r[0]), "=r"(r[1]), "=r"(r[2]), "=r"(r[3]) : "r"(addr));
}
__device__ __forceinline__ void ldsm4t(uint32_t* r, uint32_t addr) {
    asm volatile("ldmatrix.sync.aligned.m8n8.x4.trans.shared.b16 {%0,%1,%2,%3}, [%4];"
                 : "=r"(r[0]), "=r"(r[1]), "=r"(r[2]), "=r"(r[3]) : "r"(addr));
}
__device__ __forceinline__ void mma16816(float* c, const uint32_t* a, const uint32_t* b) {
    asm volatile(
        "mma.sync.aligned.m16n8k16.row.col.f32.bf16.bf16.f32 "
        "{%0,%1,%2,%3}, {%4,%5,%6,%7}, {%8,%9}, {%0,%1,%2,%3};"
        : "+f"(c[0]), "+f"(c[1]), "+f"(c[2]), "+f"(c[3])
        : "r"(a[0]), "r"(a[1]), "r"(a[2]), "r"(a[3]), "r"(b[0]), "r"(b[1]));
}

__device__ __forceinline__ uint32_t pack_bf16x2(float lo, float hi) {
    __nv_bfloat162 t = __floats2bfloat162_rn(lo, hi);
    return *reinterpret_cast<uint32_t*>(&t);
}
__device__ __forceinline__ uint32_t pack_residual(float lo, float hi, uint32_t hpack) {
    __nv_bfloat162 t = *reinterpret_cast<__nv_bfloat162*>(&hpack);
    return pack_bf16x2(lo - __low2float(t), hi - __high2float(t));
}

// ---------------------------------------------------------------------------
// Merged conversions (one launch, MLP=4 splits)
// ---------------------------------------------------------------------------
#define XSPLIT4 (MROWS * DQ / 4 / 1024)   // 2048
#define CSPLIT4 (MROWS * DC / 4 / 1024)   // 1536
#define SPLIT_BLOCKS (XSPLIT4 + CSPLIT4)  // 3584
#define CONV_BLOCKS  (SPLIT_BLOCKS + 1792)

__global__ void conv_all(const float* __restrict__ x, const float* __restrict__ ctx,
                         const float* __restrict__ Wq, const float* __restrict__ Wk,
                         const float* __restrict__ Wv, const float* __restrict__ Wo,
                         __nv_bfloat16* __restrict__ xh, __nv_bfloat16* __restrict__ xl,
                         __nv_bfloat16* __restrict__ ch, __nv_bfloat16* __restrict__ cl,
                         __nv_bfloat16* __restrict__ wqh, __nv_bfloat16* __restrict__ wql,
                         __nv_bfloat16* __restrict__ wkvh, __nv_bfloat16* __restrict__ wkvl,
                         __nv_bfloat16* __restrict__ woh, __nv_bfloat16* __restrict__ wol)
{
    int bid = blockIdx.x;
    if (bid < SPLIT_BLOCKS) {
        const float* A;
        __nv_bfloat16 *H, *L;
        int base;
        if (bid < XSPLIT4) { A = x; H = xh; L = xl; base = bid * 1024; }
        else { A = ctx; H = ch; L = cl; base = (bid - XSPLIT4) * 1024; }

        float4 v[4];
#pragma unroll
        for (int j = 0; j < 4; j++)
            v[j] = ((const float4*)A)[base + j * 256 + threadIdx.x];
#pragma unroll
        for (int j = 0; j < 4; j++) {
            const int i = base + j * 256 + threadIdx.x;
            float a[4] = {v[j].x, v[j].y, v[j].z, v[j].w};
            __nv_bfloat162 h2[2], l2[2];
#pragma unroll
            for (int k = 0; k < 2; k++) {
                __nv_bfloat16 h0 = __float2bfloat16_rn(a[2 * k]);
                __nv_bfloat16 h1 = __float2bfloat16_rn(a[2 * k + 1]);
                __nv_bfloat16 l0 = __float2bfloat16_rn(a[2 * k] - __bfloat162float(h0));
                __nv_bfloat16 l1 = __float2bfloat16_rn(a[2 * k + 1] - __bfloat162float(h1));
                h2[k] = __nv_bfloat162(h0, h1);
                l2[k] = __nv_bfloat162(l0, l1);
            }
            ((__nv_bfloat162*)H)[2 * i] = h2[0];
            ((__nv_bfloat162*)H)[2 * i + 1] = h2[1];
            ((__nv_bfloat162*)L)[2 * i] = l2[0];
            ((__nv_bfloat162*)L)[2 * i + 1] = l2[1];
        }
        return;
    }

    __shared__ float t[32][33];
    int wb = bid - SPLIT_BLOCKS;
    const float* W;
    __nv_bfloat16 *Th, *Tl;
    int K, N, loc, nx;
    if (wb < 512)       { W = Wq; Th = wqh; Tl = wql; K = DQ; N = INNER; loc = wb; nx = 16; }
    else if (wb < 896)  { W = Wk; Th = wkvh; Tl = wkvl; K = DC; N = INNER; loc = wb - 512; nx = 16; }
    else if (wb < 1280) { W = Wv; Th = wkvh + (size_t)INNER * DC; Tl = wkvl + (size_t)INNER * DC;
                          K = DC; N = INNER; loc = wb - 896; nx = 16; }
    else                { W = Wo; Th = woh; Tl = wol; K = INNER; N = DQ; loc = wb - 1280; nx = 32; }
    int n0 = (loc % nx) * 32, k0 = (loc / nx) * 32;
    int tx = threadIdx.x & 31, ty = threadIdx.x >> 5;
#pragma unroll
    for (int i = 0; i < 32; i += 8)
        t[ty + i][tx] = W[(size_t)(k0 + ty + i) * N + n0 + tx];
    __syncthreads();
#pragma unroll
    for (int i = 0; i < 32; i += 8) {
        float v = t[tx][ty + i];
        __nv_bfloat16 h = __float2bfloat16_rn(v);
        __nv_bfloat16 l = __float2bfloat16_rn(v - __bfloat162float(h));
        Th[(size_t)(n0 + ty + i) * K + k0 + tx] = h;
        Tl[(size_t)(n0 + ty + i) * K + k0 + tx] = l;
    }
}

// ---------------------------------------------------------------------------
// 3-pass split GEMM body — BK=64 chunks, pitch-72, 3-stage pipeline.
// cscale multiplies accumulators before the bf16 split-pack (used to fold
// the softmax scale into Q).
// ---------------------------------------------------------------------------
#define GP 72
#define GT64 (128 * GP)
#define GSTAGES 3
#define GEMM_DSMEM (GSTAGES * 2 * GT64 * 2)   // 110592 bytes

__device__ __forceinline__ void gemm3_body64(
    __nv_bfloat16* Asm, __nv_bfloat16* Bsm,
    const __nv_bfloat16* Ah, const __nv_bfloat16* Al,
    const __nv_bfloat16* Bh, const __nv_bfloat16* Bl,
    const float* bias, float* Cf,
    __nv_bfloat16* Ch, __nv_bfloat16* Cl,
    __nv_bfloat16* Ch2, __nv_bfloat16* Cl2,
    int N, int K, int Nsplit, int m0, int n0, float cscale)
{
    const int tid = threadIdx.x;
    const int wid = tid >> 5;
    const int lane = tid & 31;
    const int wm = wid & 3;
    const int wn = wid >> 2;

    const int nkt = K >> 6;
    const int total = 3 * nkt;

    auto issue_chunk = [&](int g, int buf) {
        const int seg = g / nkt;
        const int kt = g - seg * nkt;
        const __nv_bfloat16* Aseg = (seg == 1) ? Al : Ah;
        const __nv_bfloat16* Bseg = (seg == 2) ? Bl : Bh;
        const int k0 = kt << 6;
#pragma unroll
        for (int i = 0; i < 4; i++) {
            const int idx = tid + (i << 8);
            const int row = idx >> 3;
            const int col = (idx & 7) << 3;
            cpa16(smem_u32(Asm + buf * GT64 + row * GP + col),
                  Aseg + (size_t)(m0 + row) * K + k0 + col);
            cpa16(smem_u32(Bsm + buf * GT64 + row * GP + col),
                  Bseg + (size_t)(n0 + row) * K + k0 + col);
        }
        cpa_commit();
    };

    float acc[2][8][4];
#pragma unroll
    for (int mi = 0; mi < 2; mi++)
#pragma unroll
        for (int nj = 0; nj < 8; nj++)
#pragma unroll
            for (int r = 0; r < 4; r++) acc[mi][nj][r] = 0.f;

    const int a_r = lane & 15;
    const int a_k = (lane >> 4) << 3;
    const int b_r = ((lane >> 4) << 3) + (lane & 7);
    const int b_k = ((lane >> 3) & 1) << 3;

    issue_chunk(0, 0);
    issue_chunk(1, 1);

    int buf = 0;
    int nbuf = 2;
#pragma unroll 1
    for (int g = 0; g < total; g++) {
        if (g + 2 < total) {
            issue_chunk(g + 2, nbuf);
            cpa_wait2();
        } else {
            const int rem = total - 1 - g;
            if (rem >= 2) cpa_wait2();
            else if (rem == 1) cpa_wait1();
            else cpa_wait0();
        }
        __syncthreads();

#pragma unroll
        for (int ks = 0; ks < 4; ks++) {
            uint32_t af[2][4], bfr[4][4];
            ldsm4(af[0], smem_u32(Asm + buf * GT64 + (wm * 32 + a_r) * GP + ks * 16 + a_k));
            ldsm4(af[1], smem_u32(Asm + buf * GT64 + (wm * 32 + 16 + a_r) * GP + ks * 16 + a_k));
#pragma unroll
            for (int ni = 0; ni < 4; ni++)
                ldsm4(bfr[ni], smem_u32(Bsm + buf * GT64 + (wn * 64 + ni * 16 + b_r) * GP + ks * 16 + b_k));
#pragma unroll
            for (int mi = 0; mi < 2; mi++)
#pragma unroll
                for (int nj = 0; nj < 8; nj++)
                    mma16816(acc[mi][nj], af[mi], &bfr[nj >> 1][(nj & 1) * 2]);
        }
        __syncthreads();
        buf = (buf == GSTAGES - 1) ? 0 : buf + 1;
        nbuf = (nbuf == GSTAGES - 1) ? 0 : nbuf + 1;
    }

    const int er = lane >> 2;
    const int ec = (lane & 3) << 1;
#pragma unroll
    for (int mi = 0; mi < 2; mi++) {
        const int row = m0 + wm * 32 + mi * 16 + er;
#pragma unroll
        for (int nj = 0; nj < 8; nj++) {
            int col = n0 + wn * 64 + nj * 8 + ec;
            if (Cf) {
                float b0 = 0.f, b1 = 0.f;
                if (bias) { b0 = bias[col]; b1 = bias[col + 1]; }
                *(float2*)(Cf + (size_t)row * N + col) =
                    make_float2(acc[mi][nj][0] + b0, acc[mi][nj][1] + b1);
                *(float2*)(Cf + (size_t)(row + 8) * N + col) =
                    make_float2(acc[mi][nj][2] + b0, acc[mi][nj][3] + b1);
            } else {
                __nv_bfloat16* dh = Ch;
                __nv_bfloat16* dl = Cl;
                if (Ch2 && col >= Nsplit) { dh = Ch2; dl = Cl2; col -= Nsplit; }
                float a0 = acc[mi][nj][0] * cscale, a1 = acc[mi][nj][1] * cscale;
                float a2 = acc[mi][nj][2] * cscale, a3 = acc[mi][nj][3] * cscale;
                uint32_t h0 = pack_bf16x2(a0, a1);
                uint32_t l0 = pack_residual(a0, a1, h0);
                uint32_t h1 = pack_bf16x2(a2, a3);
                uint32_t l1 = pack_residual(a2, a3, h1);
                *(uint32_t*)(dh + (size_t)row * Nsplit + col) = h0;
                *(uint32_t*)(dl + (size_t)row * Nsplit + col) = l0;
                *(uint32_t*)(dh + (size_t)(row + 8) * Nsplit + col) = h1;
                *(uint32_t*)(dl + (size_t)(row + 8) * Nsplit + col) = l1;
            }
        }
    }
}

// Merged Q + KV projections (Q outputs pre-scaled by SCL2E)
__global__ __launch_bounds__(256, 2) void proj_qkv_kernel(
    const __nv_bfloat16* __restrict__ xh, const __nv_bfloat16* __restrict__ xl,
    const __nv_bfloat16* __restrict__ wqh, const __nv_bfloat16* __restrict__ wql,
    const __nv_bfloat16* __restrict__ ch, const __nv_bfloat16* __restrict__ cl,
    const __nv_bfloat16* __restrict__ wkvh, const __nv_bfloat16* __restrict__ wkvl,
    __nv_bfloat16* __restrict__ qh, __nv_bfloat16* __restrict__ ql,
    __nv_bfloat16* __restrict__ kh, __nv_bfloat16* __restrict__ kl,
    __nv_bfloat16* __restrict__ vh, __nv_bfloat16* __restrict__ vl)
{
    extern __shared__ __nv_bfloat16 gsm[];
    __nv_bfloat16* Asm = gsm;
    __nv_bfloat16* Bsm = gsm + GSTAGES * GT64;
    const int bid = blockIdx.x;
    if (bid < 256) {
        gemm3_body64(Asm, Bsm, xh, xl, wqh, wql, nullptr, nullptr,
                     qh, ql, nullptr, nullptr,
                     INNER, DQ, INNER, (bid >> 2) * 128, (bid & 3) * 128, SCL2E);
    } else {
        const int r = bid - 256;
        gemm3_body64(Asm, Bsm, ch, cl, wkvh, wkvl, nullptr, nullptr,
                     kh, kl, vh, vl,
                     2 * INNER, DC, INNER, (r >> 3) * 128, (r & 7) * 128, 1.0f);
    }
}

// Output projection (fp32 + bias)
__global__ __launch_bounds__(256, 2) void out_proj_kernel(
    const __nv_bfloat16* __restrict__ aoh, const __nv_bfloat16* __restrict__ aol,
    const __nv_bfloat16* __restrict__ woh, const __nv_bfloat16* __restrict__ wol,
    const float* __restrict__ bias, float* __restrict__ out)
{
    extern __shared__ __nv_bfloat16 gsm[];
    __nv_bfloat16* Asm = gsm;
    __nv_bfloat16* Bsm = gsm + GSTAGES * GT64;
    gemm3_body64(Asm, Bsm, aoh, aol, woh, wol, bias, out,
                 nullptr, nullptr, nullptr, nullptr,
                 DQ, INNER, DQ, (int)blockIdx.y * 128, (int)blockIdx.x * 128, 1.0f);
}

// ---------------------------------------------------------------------------
// Tensor-core flash attention — S arrives pre-scaled (base-2 domain).
// ---------------------------------------------------------------------------
#define FPITCH 72
#define KVT    (64 * FPITCH)
#define FLASH_SMEM ((2 * 128 * FPITCH + 2 * 4 * KVT) * 2)   // 110592 bytes

__global__ __launch_bounds__(256, 2) void flash_mma_kernel(
    const __nv_bfloat16* __restrict__ Qh_, const __nv_bfloat16* __restrict__ Ql_,
    const __nv_bfloat16* __restrict__ Kh_, const __nv_bfloat16* __restrict__ Kl_,
    const __nv_bfloat16* __restrict__ Vh_, const __nv_bfloat16* __restrict__ Vl_,
    __nv_bfloat16* __restrict__ AOh, __nv_bfloat16* __restrict__ AOl)
{
    extern __shared__ char fsmc[];
    __nv_bfloat16* fsm = (__nv_bfloat16*)fsmc;
    __nv_bfloat16* sQh = fsm;
    __nv_bfloat16* sQl = sQh + 128 * FPITCH;
    __nv_bfloat16* sKV = sQl + 128 * FPITCH;

    const int tid = threadIdx.x;
    const int wid = tid >> 5;
    const int lane = tid & 31;
    const int qt = blockIdx.x, h = blockIdx.y, b = blockIdx.z;
    const size_t qrow0 = (size_t)b * NQ + (size_t)qt * 128;
    const size_t krow0 = (size_t)b * NC;
    const int colbase = h * DIMH;

    auto issue_kv = [&](int t, int buf) {
        __nv_bfloat16* base = sKV + buf * 4 * KVT;
        const size_t gr = (krow0 + t * 64) * INNER + colbase;
#pragma unroll
        for (int i = 0; i < 2; i++) {
            const int idx = tid + (i << 8);
            const int r = idx >> 3;
            const int c = (idx & 7) << 3;
            const size_t go = gr + (size_t)r * INNER + c;
            const uint32_t so = smem_u32(base + r * FPITCH + c);
            cpa16(so + 0 * KVT * 2, Kh_ + go);
            cpa16(so + 1 * KVT * 2, Kl_ + go);
            cpa16(so + 2 * KVT * 2, Vh_ + go);
            cpa16(so + 3 * KVT * 2, Vl_ + go);
        }
        cpa_commit();
    };

#pragma unroll
    for (int i = 0; i < 4; i++) {
        const int idx = tid + (i << 8);
        const int r = idx >> 3;
        const int c = (idx & 7) << 3;
        const size_t go = (qrow0 + r) * INNER + colbase + c;
        cpa16(smem_u32(sQh + r * FPITCH + c), Qh_ + go);
        cpa16(smem_u32(sQl + r * FPITCH + c), Ql_ + go);
    }
    issue_kv(0, 0);

    const int a_r = lane & 15;
    const int a_k = (lane >> 4) << 3;
    const int b_r = ((lane >> 4) << 3) + (lane & 7);
    const int b_k = ((lane >> 3) & 1) << 3;
    const int v_r = (((lane >> 3) & 1) << 3) + (lane & 7);
    const int v_c = (lane >> 4) << 3;
    const int wq = wid * 16;

    float acc[8][4];
#pragma unroll
    for (int j = 0; j < 8; j++)
#pragma unroll
        for (int r = 0; r < 4; r++) acc[j][r] = 0.f;
    float m0 = -INFINITY, m1 = -INFINITY, l0 = 0.f, l1 = 0.f;

    const int NT = NC / 64;
#pragma unroll 1
    for (int t = 0; t < NT; t++) {
        const int buf = t & 1;
        if (t + 1 < NT) { issue_kv(t + 1, buf ^ 1); cpa_wait1(); }
        else cpa_wait0();
        __syncthreads();

        __nv_bfloat16* kh = sKV + buf * 4 * KVT;
        __nv_bfloat16* kl = kh + KVT;
        __nv_bfloat16* vh = kh + 2 * KVT;
        __nv_bfloat16* vl = kh + 3 * KVT;

        // ---- S = Qh Kh^T + Ql Kh^T + Qh Kl^T  (pre-scaled) ----
        float s[8][4];
#pragma unroll
        for (int j = 0; j < 8; j++)
#pragma unroll
            for (int r = 0; r < 4; r++) s[j][r] = 0.f;

#pragma unroll
        for (int kc = 0; kc < 4; kc++) {
            uint32_t aq[4], aql[4], bk[4][4];
            ldsm4(aq, smem_u32(&sQh[(wq + a_r) * FPITCH + kc * 16 + a_k]));
            ldsm4(aql, smem_u32(&sQl[(wq + a_r) * FPITCH + kc * 16 + a_k]));
#pragma unroll
            for (int nb = 0; nb < 4; nb++)
                ldsm4(bk[nb], smem_u32(&kh[(nb * 16 + b_r) * FPITCH + kc * 16 + b_k]));
#pragma unroll
            for (int j = 0; j < 8; j++) mma16816(s[j], aq, &bk[j >> 1][(j & 1) * 2]);
#pragma unroll
            for (int j = 0; j < 8; j++) mma16816(s[j], aql, &bk[j >> 1][(j & 1) * 2]);
#pragma unroll
            for (int nb = 0; nb < 4; nb++)
                ldsm4(bk[nb], smem_u32(&kl[(nb * 16 + b_r) * FPITCH + kc * 16 + b_k]));
#pragma unroll
            for (int j = 0; j < 8; j++) mma16816(s[j], aq, &bk[j >> 1][(j & 1) * 2]);
        }

        // ---- online softmax (base-2, no scale pass needed) ----
        float mx0 = -INFINITY, mx1 = -INFINITY;
#pragma unroll
        for (int j = 0; j < 8; j++) {
            mx0 = fmaxf(mx0, fmaxf(s[j][0], s[j][1]));
            mx1 = fmaxf(mx1, fmaxf(s[j][2], s[j][3]));
        }
        mx0 = fmaxf(mx0, __shfl_xor_sync(0xffffffffu, mx0, 1));
        mx0 = fmaxf(mx0, __shfl_xor_sync(0xffffffffu, mx0, 2));
        mx1 = fmaxf(mx1, __shfl_xor_sync(0xffffffffu, mx1, 1));
        mx1 = fmaxf(mx1, __shfl_xor_sync(0xffffffffu, mx1, 2));
        const float mn0 = fmaxf(m0, mx0);
        const float mn1 = fmaxf(m1, mx1);
        const float al0 = ex2f(m0 - mn0);
        const float al1 = ex2f(m1 - mn1);
        m0 = mn0; m1 = mn1;

        float ps0 = 0.f, ps1 = 0.f;
        uint32_t ph[8][2];
#pragma unroll
        for (int j = 0; j < 8; j++) {
            s[j][0] = ex2f(s[j][0] - mn0);
            s[j][1] = ex2f(s[j][1] - mn0);
            s[j][2] = ex2f(s[j][2] - mn1);
            s[j][3] = ex2f(s[j][3] - mn1);
            ps0 += s[j][0] + s[j][1];
            ps1 += s[j][2] + s[j][3];
            ph[j][0] = pack_bf16x2(s[j][0], s[j][1]);
            ph[j][1] = pack_bf16x2(s[j][2], s[j][3]);
        }
        l0 = l0 * al0 + ps0;
        l1 = l1 * al1 + ps1;
#pragma unroll
        for (int j = 0; j < 8; j++) {
            acc[j][0] *= al0; acc[j][1] *= al0;
            acc[j][2] *= al1; acc[j][3] *= al1;
        }

        // ---- O += Ph Vh + Pl Vh + Ph Vl ----
#pragma unroll
        for (int kc = 0; kc < 4; kc++) {
            uint32_t ap[4] = {ph[2 * kc][0], ph[2 * kc][1], ph[2 * kc + 1][0], ph[2 * kc + 1][1]};
            uint32_t apl[4];
            apl[0] = pack_residual(s[2 * kc][0], s[2 * kc][1], ph[2 * kc][0]);
            apl[1] = pack_residual(s[2 * kc][2], s[2 * kc][3], ph[2 * kc][1]);
            apl[2] = pack_residual(s[2 * kc + 1][0], s[2 * kc + 1][1], ph[2 * kc + 1][0]);
            apl[3] = pack_residual(s[2 * kc + 1][2], s[2 * kc + 1][3], ph[2 * kc + 1][1]);
            uint32_t bv[4][4];
#pragma unroll
            for (int nb = 0; nb < 4; nb++)
                ldsm4t(bv[nb], smem_u32(&vh[(kc * 16 + v_r) * FPITCH + nb * 16 + v_c]));
#pragma unroll
            for (int j = 0; j < 8; j++) mma16816(acc[j], ap, &bv[j >> 1][(j & 1) * 2]);
#pragma unroll
            for (int j = 0; j < 8; j++) mma16816(acc[j], apl, &bv[j >> 1][(j & 1) * 2]);
#pragma unroll
            for (int nb = 0; nb < 4; nb++)
                ldsm4t(bv[nb], smem_u32(&vl[(kc * 16 + v_r) * FPITCH + nb * 16 + v_c]));
#pragma unroll
            for (int j = 0; j < 8; j++) mma16816(acc[j], ap, &bv[j >> 1][(j & 1) * 2]);
        }
        __syncthreads();
    }

    l0 += __shfl_xor_sync(0xffffffffu, l0, 1);
    l0 += __shfl_xor_sync(0xffffffffu, l0, 2);
    l1 += __shfl_xor_sync(0xffffffffu, l1, 1);
    l1 += __shfl_xor_sync(0xffffffffu, l1, 2);
    const float inv0 = 1.f / l0;
    const float inv1 = 1.f / l1;
    const size_t row0 = qrow0 + wq + (lane >> 2);
    const size_t row1 = row0 + 8;
#pragma unroll
    for (int j = 0; j < 8; j++) {
        const int col = colbase + j * 8 + (lane & 3) * 2;
        float v0 = acc[j][0] * inv0, v1 = acc[j][1] * inv0;
        uint32_t hp = pack_bf16x2(v0, v1);
        *(uint32_t*)(AOh + row0 * INNER + col) = hp;
        *(uint32_t*)(AOl + row0 * INNER + col) = pack_residual(v0, v1, hp);
        float v2 = acc[j][2] * inv1, v3 = acc[j][3] * inv1;
        uint32_t hp1 = pack_bf16x2(v2, v3);
        *(uint32_t*)(AOh + row1 * INNER + col) = hp1;
        *(uint32_t*)(AOl + row1 * INNER + col) = pack_residual(v2, v3, hp1);
    }
}

// ---------------------------------------------------------------------------
extern "C" void kernel_launch(void* const* d_in, const int* in_sizes, int n_in,
                              void* d_out, int out_size)
{
    const float* x   = (const float*)d_in[0];
    const float* ctx = (const float*)d_in[1];
    const float* Wq  = (const float*)d_in[2];
    const float* Wk  = (const float*)d_in[3];
    const float* Wv  = (const float*)d_in[4];
    const float* Wo  = (const float*)d_in[5];
    const float* bo  = (const float*)d_in[6];
    float* out = (float*)d_out;

    __nv_bfloat16 *xh, *xl, *ch, *cl;
    __nv_bfloat16 *qh, *ql, *kh, *kl, *vh, *vl, *aoh, *aol;
    __nv_bfloat16 *wqh, *wql, *wkvh, *wkvl, *woh, *wol;
    cudaGetSymbolAddress((void**)&xh, g_xh);   cudaGetSymbolAddress((void**)&xl, g_xl);
    cudaGetSymbolAddress((void**)&ch, g_ch);   cudaGetSymbolAddress((void**)&cl, g_cl);
    cudaGetSymbolAddress((void**)&qh, g_qh);   cudaGetSymbolAddress((void**)&ql, g_ql);
    cudaGetSymbolAddress((void**)&kh, g_kh);   cudaGetSymbolAddress((void**)&kl, g_kl);
    cudaGetSymbolAddress((void**)&vh, g_vh);   cudaGetSymbolAddress((void**)&vl, g_vl);
    cudaGetSymbolAddress((void**)&aoh, g_aoh); cudaGetSymbolAddress((void**)&aol, g_aol);
    cudaGetSymbolAddress((void**)&wqh, g_wqh); cudaGetSymbolAddress((void**)&wql, g_wql);
    cudaGetSymbolAddress((void**)&wkvh, g_wkvh); cudaGetSymbolAddress((void**)&wkvl, g_wkvl);
    cudaGetSymbolAddress((void**)&woh, g_woh); cudaGetSymbolAddress((void**)&wol, g_wol);

    // ---- conversions ----
    conv_all<<<CONV_BLOCKS, 256>>>(x, ctx, Wq, Wk, Wv, Wo,
                                   xh, xl, ch, cl, wqh, wql, wkvh, wkvl, woh, wol);

    // ---- Q + KV projections (BK=64, 3-stage) ----
    cudaFuncSetAttribute(proj_qkv_kernel, cudaFuncAttributeMaxDynamicSharedMemorySize,
                         GEMM_DSMEM);
    proj_qkv_kernel<<<768, 256, GEMM_DSMEM>>>(xh, xl, wqh, wql, ch, cl, wkvh, wkvl,
                                              qh, ql, kh, kl, vh, vl);

    // ---- flash attention ----
    cudaFuncSetAttribute(flash_mma_kernel, cudaFuncAttributeMaxDynamicSharedMemorySize,
                         FLASH_SMEM);
    flash_mma_kernel<<<dim3(NQ / 128, NHEADS, BATCH), 256, FLASH_SMEM>>>(
        qh, ql, kh, kl, vh, vl, aoh, aol);

    // ---- output projection (BK=64, 3-stage) ----
    cudaFuncSetAttribute(out_proj_kernel, cudaFuncAttributeMaxDynamicSharedMemorySize,
                         GEMM_DSMEM);
    out_proj_kernel<<<dim3(DQ / 128, MROWS / 128), 256, GEMM_DSMEM>>>(
        aoh, aol, woh, wol, bo, out);
}

// round 15
// speedup vs baseline: 1.0474x; 1.0474x over previous
#include <cuda_runtime.h>
#include <cuda_bf16.h>
#include <math.h>
#include <stdint.h>

#define NHEADS 8
#define DIMH   64
#define BATCH  4
#define NQ     2048
#define NC     2048
#define DQ     1024
#define DC     768
#define INNER  512
#define MROWS  (BATCH * NQ)   // 8192

#define SCL2E 0.18033688f   // SCALE * log2(e), folded into Q projection

// ---------------------------------------------------------------------------
// Scratch
// ---------------------------------------------------------------------------
__device__ __nv_bfloat16 g_xh[MROWS * DQ];
__device__ __nv_bfloat16 g_xl[MROWS * DQ];
__device__ __nv_bfloat16 g_ch[MROWS * DC];
__device__ __nv_bfloat16 g_cl[MROWS * DC];

__device__ __nv_bfloat16 g_qh[MROWS * INNER];
__device__ __nv_bfloat16 g_ql[MROWS * INNER];
__device__ __nv_bfloat16 g_kh[MROWS * INNER];
__device__ __nv_bfloat16 g_kl[MROWS * INNER];
__device__ __nv_bfloat16 g_vh[MROWS * INNER];
__device__ __nv_bfloat16 g_vl[MROWS * INNER];
__device__ __nv_bfloat16 g_aoh[MROWS * INNER];
__device__ __nv_bfloat16 g_aol[MROWS * INNER];

__device__ __nv_bfloat16 g_wqh[INNER * DQ];
__device__ __nv_bfloat16 g_wql[INNER * DQ];
__device__ __nv_bfloat16 g_wkvh[2 * INNER * DC];
__device__ __nv_bfloat16 g_wkvl[2 * INNER * DC];
__device__ __nv_bfloat16 g_woh[DQ * INNER];
__device__ __nv_bfloat16 g_wol[DQ * INNER];

// ---------------------------------------------------------------------------
// PTX helpers
// ---------------------------------------------------------------------------
__device__ __forceinline__ uint32_t smem_u32(const void* p) {
    uint32_t a;
    asm("{ .reg .u64 t; cvta.to.shared.u64 t, %1; cvt.u32.u64 %0, t; }" : "=r"(a) : "l"(p));
    return a;
}
__device__ __forceinline__ void cpa16(uint32_t dst, const void* src) {
    asm volatile("cp.async.cg.shared.global [%0], [%1], 16;" :: "r"(dst), "l"(src));
}
__device__ __forceinline__ void cpa_commit() { asm volatile("cp.async.commit_group;" ::: "memory"); }
__device__ __forceinline__ void cpa_wait0()  { asm volatile("cp.async.wait_group 0;" ::: "memory"); }
__device__ __forceinline__ void cpa_wait1()  { asm volatile("cp.async.wait_group 1;" ::: "memory"); }

__device__ __forceinline__ float ex2f(float x) {
    float y;
    asm("ex2.approx.f32 %0, %1;" : "=f"(y) : "f"(x));
    return y;
}

__device__ __forceinline__ void ldsm4(uint32_t* r, uint32_t addr) {
    asm volatile("ldmatrix.sync.aligned.m8n8.x4.shared.b16 {%0,%1,%2,%3}, [%4];"
                 : "=r"(r[0]), "=r"(r[1]), "=r"(r[2]), "=r"(r[3]) : "r"(addr));
}
__device__ __forceinline__ void ldsm4t(uint32_t* r, uint32_t addr) {
    asm volatile("ldmatrix.sync.aligned.m8n8.x4.trans.shared.b16 {%0,%1,%2,%3}, [%4];"
                 : "=r"(r[0]), "=r"(r[1]), "=r"(r[2]), "=r"(r[3]) : "r"(addr));
}
__device__ __forceinline__ void mma16816(float* c, const uint32_t* a, const uint32_t* b) {
    asm volatile(
        "mma.sync.aligned.m16n8k16.row.col.f32.bf16.bf16.f32 "
        "{%0,%1,%2,%3}, {%4,%5,%6,%7}, {%8,%9}, {%0,%1,%2,%3};"
        : "+f"(c[0]), "+f"(c[1]), "+f"(c[2]), "+f"(c[3])
        : "r"(a[0]), "r"(a[1]), "r"(a[2]), "r"(a[3]), "r"(b[0]), "r"(b[1]));
}

__device__ __forceinline__ uint32_t pack_bf16x2(float lo, float hi) {
    __nv_bfloat162 t = __floats2bfloat162_rn(lo, hi);
    return *reinterpret_cast<uint32_t*>(&t);
}
__device__ __forceinline__ uint32_t pack_residual(float lo, float hi, uint32_t hpack) {
    __nv_bfloat162 t = *reinterpret_cast<__nv_bfloat162*>(&hpack);
    return pack_bf16x2(lo - __low2float(t), hi - __high2float(t));
}

// ---------------------------------------------------------------------------
// Merged conversions (one launch, MLP=4 splits)
// ---------------------------------------------------------------------------
#define XSPLIT4 (MROWS * DQ / 4 / 1024)   // 2048
#define CSPLIT4 (MROWS * DC / 4 / 1024)   // 1536
#define SPLIT_BLOCKS (XSPLIT4 + CSPLIT4)  // 3584
#define CONV_BLOCKS  (SPLIT_BLOCKS + 1792)

__global__ void conv_all(const float* __restrict__ x, const float* __restrict__ ctx,
                         const float* __restrict__ Wq, const float* __restrict__ Wk,
                         const float* __restrict__ Wv, const float* __restrict__ Wo,
                         __nv_bfloat16* __restrict__ xh, __nv_bfloat16* __restrict__ xl,
                         __nv_bfloat16* __restrict__ ch, __nv_bfloat16* __restrict__ cl,
                         __nv_bfloat16* __restrict__ wqh, __nv_bfloat16* __restrict__ wql,
                         __nv_bfloat16* __restrict__ wkvh, __nv_bfloat16* __restrict__ wkvl,
                         __nv_bfloat16* __restrict__ woh, __nv_bfloat16* __restrict__ wol)
{
    int bid = blockIdx.x;
    if (bid < SPLIT_BLOCKS) {
        const float* A;
        __nv_bfloat16 *H, *L;
        int base;
        if (bid < XSPLIT4) { A = x; H = xh; L = xl; base = bid * 1024; }
        else { A = ctx; H = ch; L = cl; base = (bid - XSPLIT4) * 1024; }

        float4 v[4];
#pragma unroll
        for (int j = 0; j < 4; j++)
            v[j] = ((const float4*)A)[base + j * 256 + threadIdx.x];
#pragma unroll
        for (int j = 0; j < 4; j++) {
            const int i = base + j * 256 + threadIdx.x;
            float a[4] = {v[j].x, v[j].y, v[j].z, v[j].w};
            __nv_bfloat162 h2[2], l2[2];
#pragma unroll
            for (int k = 0; k < 2; k++) {
                __nv_bfloat16 h0 = __float2bfloat16_rn(a[2 * k]);
                __nv_bfloat16 h1 = __float2bfloat16_rn(a[2 * k + 1]);
                __nv_bfloat16 l0 = __float2bfloat16_rn(a[2 * k] - __bfloat162float(h0));
                __nv_bfloat16 l1 = __float2bfloat16_rn(a[2 * k + 1] - __bfloat162float(h1));
                h2[k] = __nv_bfloat162(h0, h1);
                l2[k] = __nv_bfloat162(l0, l1);
            }
            ((__nv_bfloat162*)H)[2 * i] = h2[0];
            ((__nv_bfloat162*)H)[2 * i + 1] = h2[1];
            ((__nv_bfloat162*)L)[2 * i] = l2[0];
            ((__nv_bfloat162*)L)[2 * i + 1] = l2[1];
        }
        return;
    }

    __shared__ float t[32][33];
    int wb = bid - SPLIT_BLOCKS;
    const float* W;
    __nv_bfloat16 *Th, *Tl;
    int K, N, loc, nx;
    if (wb < 512)       { W = Wq; Th = wqh; Tl = wql; K = DQ; N = INNER; loc = wb; nx = 16; }
    else if (wb < 896)  { W = Wk; Th = wkvh; Tl = wkvl; K = DC; N = INNER; loc = wb - 512; nx = 16; }
    else if (wb < 1280) { W = Wv; Th = wkvh + (size_t)INNER * DC; Tl = wkvl + (size_t)INNER * DC;
                          K = DC; N = INNER; loc = wb - 896; nx = 16; }
    else                { W = Wo; Th = woh; Tl = wol; K = INNER; N = DQ; loc = wb - 1280; nx = 32; }
    int n0 = (loc % nx) * 32, k0 = (loc / nx) * 32;
    int tx = threadIdx.x & 31, ty = threadIdx.x >> 5;
#pragma unroll
    for (int i = 0; i < 32; i += 8)
        t[ty + i][tx] = W[(size_t)(k0 + ty + i) * N + n0 + tx];
    __syncthreads();
#pragma unroll
    for (int i = 0; i < 32; i += 8) {
        float v = t[tx][ty + i];
        __nv_bfloat16 h = __float2bfloat16_rn(v);
        __nv_bfloat16 l = __float2bfloat16_rn(v - __bfloat162float(h));
        Th[(size_t)(n0 + ty + i) * K + k0 + tx] = h;
        Tl[(size_t)(n0 + ty + i) * K + k0 + tx] = l;
    }
}

// ---------------------------------------------------------------------------
// 2-pass split GEMM: pass1 loads (Ah,Bh,Bl), computes AhBh+AhBl;
//                    pass2 loads (Al,Bh), computes AlBh.
// BK=64, pitch-72, 2-stage. Smem = 2 stages * 3 tiles * 18432B = 110592 B.
// ---------------------------------------------------------------------------
#define GP 72
#define GT64 (128 * GP)
#define GEMM_DSMEM (2 * 3 * GT64 * 2)   // 110592 bytes

__device__ __forceinline__ void gemm2p_body(
    __nv_bfloat16* sm,   // [2][3][GT64]
    const __nv_bfloat16* Ah, const __nv_bfloat16* Al,
    const __nv_bfloat16* Bh, const __nv_bfloat16* Bl,
    const float* bias, float* Cf,
    __nv_bfloat16* Ch, __nv_bfloat16* Cl,
    __nv_bfloat16* Ch2, __nv_bfloat16* Cl2,
    int N, int K, int Nsplit, int m0, int n0, float cscale)
{
    const int tid = threadIdx.x;
    const int wid = tid >> 5;
    const int lane = tid & 31;
    const int wm = wid & 3;
    const int wn = wid >> 2;

    const int nkt = K >> 6;
    const int total = 2 * nkt;

    auto issue_chunk = [&](int g, int buf) {
        const bool p2 = g >= nkt;
        const int kt = p2 ? g - nkt : g;
        const int k0 = kt << 6;
        const __nv_bfloat16* As = p2 ? Al : Ah;
        __nv_bfloat16* base = sm + buf * 3 * GT64;
#pragma unroll
        for (int i = 0; i < 4; i++) {
            const int idx = tid + (i << 8);
            const int row = idx >> 3;
            const int col = (idx & 7) << 3;
            cpa16(smem_u32(base + row * GP + col),
                  As + (size_t)(m0 + row) * K + k0 + col);
            cpa16(smem_u32(base + GT64 + row * GP + col),
                  Bh + (size_t)(n0 + row) * K + k0 + col);
        }
        if (!p2) {
#pragma unroll
            for (int i = 0; i < 4; i++) {
                const int idx = tid + (i << 8);
                const int row = idx >> 3;
                const int col = (idx & 7) << 3;
                cpa16(smem_u32(base + 2 * GT64 + row * GP + col),
                      Bl + (size_t)(n0 + row) * K + k0 + col);
            }
        }
        cpa_commit();
    };

    float acc[2][8][4];
#pragma unroll
    for (int mi = 0; mi < 2; mi++)
#pragma unroll
        for (int nj = 0; nj < 8; nj++)
#pragma unroll
            for (int r = 0; r < 4; r++) acc[mi][nj][r] = 0.f;

    const int a_r = lane & 15;
    const int a_k = (lane >> 4) << 3;
    const int b_r = ((lane >> 4) << 3) + (lane & 7);
    const int b_k = ((lane >> 3) & 1) << 3;

    issue_chunk(0, 0);
#pragma unroll 1
    for (int g = 0; g < total; g++) {
        const int buf = g & 1;
        if (g + 1 < total) { issue_chunk(g + 1, buf ^ 1); cpa_wait1(); }
        else cpa_wait0();
        __syncthreads();

        __nv_bfloat16* base = sm + buf * 3 * GT64;
        const bool p1 = g < nkt;
#pragma unroll
        for (int ks = 0; ks < 4; ks++) {
            uint32_t af[2][4], bfr[4][4];
            ldsm4(af[0], smem_u32(base + (wm * 32 + a_r) * GP + ks * 16 + a_k));
            ldsm4(af[1], smem_u32(base + (wm * 32 + 16 + a_r) * GP + ks * 16 + a_k));
#pragma unroll
            for (int ni = 0; ni < 4; ni++)
                ldsm4(bfr[ni], smem_u32(base + GT64 + (wn * 64 + ni * 16 + b_r) * GP + ks * 16 + b_k));
#pragma unroll
            for (int mi = 0; mi < 2; mi++)
#pragma unroll
                for (int nj = 0; nj < 8; nj++)
                    mma16816(acc[mi][nj], af[mi], &bfr[nj >> 1][(nj & 1) * 2]);
            if (p1) {
#pragma unroll
                for (int ni = 0; ni < 4; ni++)
                    ldsm4(bfr[ni], smem_u32(base + 2 * GT64 + (wn * 64 + ni * 16 + b_r) * GP + ks * 16 + b_k));
#pragma unroll
                for (int mi = 0; mi < 2; mi++)
#pragma unroll
                    for (int nj = 0; nj < 8; nj++)
                        mma16816(acc[mi][nj], af[mi], &bfr[nj >> 1][(nj & 1) * 2]);
            }
        }
        __syncthreads();
    }

    const int er = lane >> 2;
    const int ec = (lane & 3) << 1;
#pragma unroll
    for (int mi = 0; mi < 2; mi++) {
        const int row = m0 + wm * 32 + mi * 16 + er;
#pragma unroll
        for (int nj = 0; nj < 8; nj++) {
            int col = n0 + wn * 64 + nj * 8 + ec;
            if (Cf) {
                float b0 = 0.f, b1 = 0.f;
                if (bias) { b0 = bias[col]; b1 = bias[col + 1]; }
                *(float2*)(Cf + (size_t)row * N + col) =
                    make_float2(acc[mi][nj][0] + b0, acc[mi][nj][1] + b1);
                *(float2*)(Cf + (size_t)(row + 8) * N + col) =
                    make_float2(acc[mi][nj][2] + b0, acc[mi][nj][3] + b1);
            } else {
                __nv_bfloat16* dh = Ch;
                __nv_bfloat16* dl = Cl;
                if (Ch2 && col >= Nsplit) { dh = Ch2; dl = Cl2; col -= Nsplit; }
                float a0 = acc[mi][nj][0] * cscale, a1 = acc[mi][nj][1] * cscale;
                float a2 = acc[mi][nj][2] * cscale, a3 = acc[mi][nj][3] * cscale;
                uint32_t h0 = pack_bf16x2(a0, a1);
                uint32_t l0 = pack_residual(a0, a1, h0);
                uint32_t h1 = pack_bf16x2(a2, a3);
                uint32_t l1 = pack_residual(a2, a3, h1);
                *(uint32_t*)(dh + (size_t)row * Nsplit + col) = h0;
                *(uint32_t*)(dl + (size_t)row * Nsplit + col) = l0;
                *(uint32_t*)(dh + (size_t)(row + 8) * Nsplit + col) = h1;
                *(uint32_t*)(dl + (size_t)(row + 8) * Nsplit + col) = l1;
            }
        }
    }
}

// Merged Q + KV projections (Q outputs pre-scaled by SCL2E)
__global__ __launch_bounds__(256, 2) void proj_qkv_kernel(
    const __nv_bfloat16* __restrict__ xh, const __nv_bfloat16* __restrict__ xl,
    const __nv_bfloat16* __restrict__ wqh, const __nv_bfloat16* __restrict__ wql,
    const __nv_bfloat16* __restrict__ ch, const __nv_bfloat16* __restrict__ cl,
    const __nv_bfloat16* __restrict__ wkvh, const __nv_bfloat16* __restrict__ wkvl,
    __nv_bfloat16* __restrict__ qh, __nv_bfloat16* __restrict__ ql,
    __nv_bfloat16* __restrict__ kh, __nv_bfloat16* __restrict__ kl,
    __nv_bfloat16* __restrict__ vh, __nv_bfloat16* __restrict__ vl)
{
    extern __shared__ __nv_bfloat16 gsm[];
    const int bid = blockIdx.x;
    if (bid < 256) {
        gemm2p_body(gsm, xh, xl, wqh, wql, nullptr, nullptr,
                    qh, ql, nullptr, nullptr,
                    INNER, DQ, INNER, (bid >> 2) * 128, (bid & 3) * 128, SCL2E);
    } else {
        const int r = bid - 256;
        gemm2p_body(gsm, ch, cl, wkvh, wkvl, nullptr, nullptr,
                    kh, kl, vh, vl,
                    2 * INNER, DC, INNER, (r >> 3) * 128, (r & 7) * 128, 1.0f);
    }
}

// Output projection (fp32 + bias)
__global__ __launch_bounds__(256, 2) void out_proj_kernel(
    const __nv_bfloat16* __restrict__ aoh, const __nv_bfloat16* __restrict__ aol,
    const __nv_bfloat16* __restrict__ woh, const __nv_bfloat16* __restrict__ wol,
    const float* __restrict__ bias, float* __restrict__ out)
{
    extern __shared__ __nv_bfloat16 gsm[];
    gemm2p_body(gsm, aoh, aol, woh, wol, bias, out,
                nullptr, nullptr, nullptr, nullptr,
                DQ, INNER, DQ, (int)blockIdx.y * 128, (int)blockIdx.x * 128, 1.0f);
}

// ---------------------------------------------------------------------------
// Tensor-core flash attention — S arrives pre-scaled (base-2 domain).
// ---------------------------------------------------------------------------
#define FPITCH 72
#define KVT    (64 * FPITCH)
#define FLASH_SMEM ((2 * 128 * FPITCH + 2 * 4 * KVT) * 2)   // 110592 bytes

__global__ __launch_bounds__(256, 2) void flash_mma_kernel(
    const __nv_bfloat16* __restrict__ Qh_, const __nv_bfloat16* __restrict__ Ql_,
    const __nv_bfloat16* __restrict__ Kh_, const __nv_bfloat16* __restrict__ Kl_,
    const __nv_bfloat16* __restrict__ Vh_, const __nv_bfloat16* __restrict__ Vl_,
    __nv_bfloat16* __restrict__ AOh, __nv_bfloat16* __restrict__ AOl)
{
    extern __shared__ char fsmc[];
    __nv_bfloat16* fsm = (__nv_bfloat16*)fsmc;
    __nv_bfloat16* sQh = fsm;
    __nv_bfloat16* sQl = sQh + 128 * FPITCH;
    __nv_bfloat16* sKV = sQl + 128 * FPITCH;

    const int tid = threadIdx.x;
    const int wid = tid >> 5;
    const int lane = tid & 31;
    const int qt = blockIdx.x, h = blockIdx.y, b = blockIdx.z;
    const size_t qrow0 = (size_t)b * NQ + (size_t)qt * 128;
    const size_t krow0 = (size_t)b * NC;
    const int colbase = h * DIMH;

    auto issue_kv = [&](int t, int buf) {
        __nv_bfloat16* base = sKV + buf * 4 * KVT;
        const size_t gr = (krow0 + t * 64) * INNER + colbase;
#pragma unroll
        for (int i = 0; i < 2; i++) {
            const int idx = tid + (i << 8);
            const int r = idx >> 3;
            const int c = (idx & 7) << 3;
            const size_t go = gr + (size_t)r * INNER + c;
            const uint32_t so = smem_u32(base + r * FPITCH + c);
            cpa16(so + 0 * KVT * 2, Kh_ + go);
            cpa16(so + 1 * KVT * 2, Kl_ + go);
            cpa16(so + 2 * KVT * 2, Vh_ + go);
            cpa16(so + 3 * KVT * 2, Vl_ + go);
        }
        cpa_commit();
    };

#pragma unroll
    for (int i = 0; i < 4; i++) {
        const int idx = tid + (i << 8);
        const int r = idx >> 3;
        const int c = (idx & 7) << 3;
        const size_t go = (qrow0 + r) * INNER + colbase + c;
        cpa16(smem_u32(sQh + r * FPITCH + c), Qh_ + go);
        cpa16(smem_u32(sQl + r * FPITCH + c), Ql_ + go);
    }
    issue_kv(0, 0);

    const int a_r = lane & 15;
    const int a_k = (lane >> 4) << 3;
    const int b_r = ((lane >> 4) << 3) + (lane & 7);
    const int b_k = ((lane >> 3) & 1) << 3;
    const int v_r = (((lane >> 3) & 1) << 3) + (lane & 7);
    const int v_c = (lane >> 4) << 3;
    const int wq = wid * 16;

    float acc[8][4];
#pragma unroll
    for (int j = 0; j < 8; j++)
#pragma unroll
        for (int r = 0; r < 4; r++) acc[j][r] = 0.f;
    float m0 = -INFINITY, m1 = -INFINITY, l0 = 0.f, l1 = 0.f;

    const int NT = NC / 64;
#pragma unroll 1
    for (int t = 0; t < NT; t++) {
        const int buf = t & 1;
        if (t + 1 < NT) { issue_kv(t + 1, buf ^ 1); cpa_wait1(); }
        else cpa_wait0();
        __syncthreads();

        __nv_bfloat16* kh = sKV + buf * 4 * KVT;
        __nv_bfloat16* kl = kh + KVT;
        __nv_bfloat16* vh = kh + 2 * KVT;
        __nv_bfloat16* vl = kh + 3 * KVT;

        float s[8][4];
#pragma unroll
        for (int j = 0; j < 8; j++)
#pragma unroll
            for (int r = 0; r < 4; r++) s[j][r] = 0.f;

#pragma unroll
        for (int kc = 0; kc < 4; kc++) {
            uint32_t aq[4], aql[4], bk[4][4];
            ldsm4(aq, smem_u32(&sQh[(wq + a_r) * FPITCH + kc * 16 + a_k]));
            ldsm4(aql, smem_u32(&sQl[(wq + a_r) * FPITCH + kc * 16 + a_k]));
#pragma unroll
            for (int nb = 0; nb < 4; nb++)
                ldsm4(bk[nb], smem_u32(&kh[(nb * 16 + b_r) * FPITCH + kc * 16 + b_k]));
#pragma unroll
            for (int j = 0; j < 8; j++) mma16816(s[j], aq, &bk[j >> 1][(j & 1) * 2]);
#pragma unroll
            for (int j = 0; j < 8; j++) mma16816(s[j], aql, &bk[j >> 1][(j & 1) * 2]);
#pragma unroll
            for (int nb = 0; nb < 4; nb++)
                ldsm4(bk[nb], smem_u32(&kl[(nb * 16 + b_r) * FPITCH + kc * 16 + b_k]));
#pragma unroll
            for (int j = 0; j < 8; j++) mma16816(s[j], aq, &bk[j >> 1][(j & 1) * 2]);
        }

        float mx0 = -INFINITY, mx1 = -INFINITY;
#pragma unroll
        for (int j = 0; j < 8; j++) {
            mx0 = fmaxf(mx0, fmaxf(s[j][0], s[j][1]));
            mx1 = fmaxf(mx1, fmaxf(s[j][2], s[j][3]));
        }
        mx0 = fmaxf(mx0, __shfl_xor_sync(0xffffffffu, mx0, 1));
        mx0 = fmaxf(mx0, __shfl_xor_sync(0xffffffffu, mx0, 2));
        mx1 = fmaxf(mx1, __shfl_xor_sync(0xffffffffu, mx1, 1));
        mx1 = fmaxf(mx1, __shfl_xor_sync(0xffffffffu, mx1, 2));
        const float mn0 = fmaxf(m0, mx0);
        const float mn1 = fmaxf(m1, mx1);
        const float al0 = ex2f(m0 - mn0);
        const float al1 = ex2f(m1 - mn1);
        m0 = mn0; m1 = mn1;

        float ps0 = 0.f, ps1 = 0.f;
        uint32_t ph[8][2];
#pragma unroll
        for (int j = 0; j < 8; j++) {
            s[j][0] = ex2f(s[j][0] - mn0);
            s[j][1] = ex2f(s[j][1] - mn0);
            s[j][2] = ex2f(s[j][2] - mn1);
            s[j][3] = ex2f(s[j][3] - mn1);
            ps0 += s[j][0] + s[j][1];
            ps1 += s[j][2] + s[j][3];
            ph[j][0] = pack_bf16x2(s[j][0], s[j][1]);
            ph[j][1] = pack_bf16x2(s[j][2], s[j][3]);
        }
        l0 = l0 * al0 + ps0;
        l1 = l1 * al1 + ps1;
#pragma unroll
        for (int j = 0; j < 8; j++) {
            acc[j][0] *= al0; acc[j][1] *= al0;
            acc[j][2] *= al1; acc[j][3] *= al1;
        }

#pragma unroll
        for (int kc = 0; kc < 4; kc++) {
            uint32_t ap[4] = {ph[2 * kc][0], ph[2 * kc][1], ph[2 * kc + 1][0], ph[2 * kc + 1][1]};
            uint32_t apl[4];
            apl[0] = pack_residual(s[2 * kc][0], s[2 * kc][1], ph[2 * kc][0]);
            apl[1] = pack_residual(s[2 * kc][2], s[2 * kc][3], ph[2 * kc][1]);
            apl[2] = pack_residual(s[2 * kc + 1][0], s[2 * kc + 1][1], ph[2 * kc + 1][0]);
            apl[3] = pack_residual(s[2 * kc + 1][2], s[2 * kc + 1][3], ph[2 * kc + 1][1]);
            uint32_t bv[4][4];
#pragma unroll
            for (int nb = 0; nb < 4; nb++)
                ldsm4t(bv[nb], smem_u32(&vh[(kc * 16 + v_r) * FPITCH + nb * 16 + v_c]));
#pragma unroll
            for (int j = 0; j < 8; j++) mma16816(acc[j], ap, &bv[j >> 1][(j & 1) * 2]);
#pragma unroll
            for (int j = 0; j < 8; j++) mma16816(acc[j], apl, &bv[j >> 1][(j & 1) * 2]);
#pragma unroll
            for (int nb = 0; nb < 4; nb++)
                ldsm4t(bv[nb], smem_u32(&vl[(kc * 16 + v_r) * FPITCH + nb * 16 + v_c]));
#pragma unroll
            for (int j = 0; j < 8; j++) mma16816(acc[j], ap, &bv[j >> 1][(j & 1) * 2]);
        }
        __syncthreads();
    }

    l0 += __shfl_xor_sync(0xffffffffu, l0, 1);
    l0 += __shfl_xor_sync(0xffffffffu, l0, 2);
    l1 += __shfl_xor_sync(0xffffffffu, l1, 1);
    l1 += __shfl_xor_sync(0xffffffffu, l1, 2);
    const float inv0 = 1.f / l0;
    const float inv1 = 1.f / l1;
    const size_t row0 = qrow0 + wq + (lane >> 2);
    const size_t row1 = row0 + 8;
#pragma unroll
    for (int j = 0; j < 8; j++) {
        const int col = colbase + j * 8 + (lane & 3) * 2;
        float v0 = acc[j][0] * inv0, v1 = acc[j][1] * inv0;
        uint32_t hp = pack_bf16x2(v0, v1);
        *(uint32_t*)(AOh + row0 * INNER + col) = hp;
        *(uint32_t*)(AOl + row0 * INNER + col) = pack_residual(v0, v1, hp);
        float v2 = acc[j][2] * inv1, v3 = acc[j][3] * inv1;
        uint32_t hp1 = pack_bf16x2(v2, v3);
        *(uint32_t*)(AOh + row1 * INNER + col) = hp1;
        *(uint32_t*)(AOl + row1 * INNER + col) = pack_residual(v2, v3, hp1);
    }
}

// ---------------------------------------------------------------------------
extern "C" void kernel_launch(void* const* d_in, const int* in_sizes, int n_in,
                              void* d_out, int out_size)
{
    const float* x   = (const float*)d_in[0];
    const float* ctx = (const float*)d_in[1];
    const float* Wq  = (const float*)d_in[2];
    const float* Wk  = (const float*)d_in[3];
    const float* Wv  = (const float*)d_in[4];
    const float* Wo  = (const float*)d_in[5];
    const float* bo  = (const float*)d_in[6];
    float* out = (float*)d_out;

    __nv_bfloat16 *xh, *xl, *ch, *cl;
    __nv_bfloat16 *qh, *ql, *kh, *kl, *vh, *vl, *aoh, *aol;
    __nv_bfloat16 *wqh, *wql, *wkvh, *wkvl, *woh, *wol;
    cudaGetSymbolAddress((void**)&xh, g_xh);   cudaGetSymbolAddress((void**)&xl, g_xl);
    cudaGetSymbolAddress((void**)&ch, g_ch);   cudaGetSymbolAddress((void**)&cl, g_cl);
    cudaGetSymbolAddress((void**)&qh, g_qh);   cudaGetSymbolAddress((void**)&ql, g_ql);
    cudaGetSymbolAddress((void**)&kh, g_kh);   cudaGetSymbolAddress((void**)&kl, g_kl);
    cudaGetSymbolAddress((void**)&vh, g_vh);   cudaGetSymbolAddress((void**)&vl, g_vl);
    cudaGetSymbolAddress((void**)&aoh, g_aoh); cudaGetSymbolAddress((void**)&aol, g_aol);
    cudaGetSymbolAddress((void**)&wqh, g_wqh); cudaGetSymbolAddress((void**)&wql, g_wql);
    cudaGetSymbolAddress((void**)&wkvh, g_wkvh); cudaGetSymbolAddress((void**)&wkvl, g_wkvl);
    cudaGetSymbolAddress((void**)&woh, g_woh); cudaGetSymbolAddress((void**)&wol, g_wol);

    // ---- conversions ----
    conv_all<<<CONV_BLOCKS, 256>>>(x, ctx, Wq, Wk, Wv, Wo,
                                   xh, xl, ch, cl, wqh, wql, wkvh, wkvl, woh, wol);

    // ---- Q + KV projections (2-pass, BK=64, 2-stage) ----
    cudaFuncSetAttribute(proj_qkv_kernel, cudaFuncAttributeMaxDynamicSharedMemorySize,
                         GEMM_DSMEM);
    proj_qkv_kernel<<<768, 256, GEMM_DSMEM>>>(xh, xl, wqh, wql, ch, cl, wkvh, wkvl,
                                              qh, ql, kh, kl, vh, vl);

    // ---- flash attention ----
    cudaFuncSetAttribute(flash_mma_kernel, cudaFuncAttributeMaxDynamicSharedMemorySize,
                         FLASH_SMEM);
    flash_mma_kernel<<<dim3(NQ / 128, NHEADS, BATCH), 256, FLASH_SMEM>>>(
        qh, ql, kh, kl, vh, vl, aoh, aol);

    // ---- output projection (2-pass, BK=64, 2-stage) ----
    cudaFuncSetAttribute(out_proj_kernel, cudaFuncAttributeMaxDynamicSharedMemorySize,
                         GEMM_DSMEM);
    out_proj_kernel<<<dim3(DQ / 128, MROWS / 128), 256, GEMM_DSMEM>>>(
        aoh, aol, woh, wol, bo, out);
}

// round 16
// speedup vs baseline: 1.0603x; 1.0123x over previous
#include <cuda_runtime.h>
#include <cuda_bf16.h>
#include <math.h>
#include <stdint.h>

#define NHEADS 8
#define DIMH   64
#define BATCH  4
#define NQ     2048
#define NC     2048
#define DQ     1024
#define DC     768
#define INNER  512
#define MROWS  (BATCH * NQ)   // 8192

#define SCL2E 0.18033688f   // SCALE * log2(e), folded into Q projection

// ---------------------------------------------------------------------------
// Scratch
// ---------------------------------------------------------------------------
__device__ __nv_bfloat16 g_xh[MROWS * DQ];
__device__ __nv_bfloat16 g_xl[MROWS * DQ];
__device__ __nv_bfloat16 g_ch[MROWS * DC];
__device__ __nv_bfloat16 g_cl[MROWS * DC];

__device__ __nv_bfloat16 g_qh[MROWS * INNER];
__device__ __nv_bfloat16 g_ql[MROWS * INNER];
__device__ __nv_bfloat16 g_kh[MROWS * INNER];
__device__ __nv_bfloat16 g_kl[MROWS * INNER];
__device__ __nv_bfloat16 g_vh[MROWS * INNER];
__device__ __nv_bfloat16 g_vl[MROWS * INNER];
__device__ __nv_bfloat16 g_aoh[MROWS * INNER];
__device__ __nv_bfloat16 g_aol[MROWS * INNER];

__device__ __nv_bfloat16 g_wqh[INNER * DQ];
__device__ __nv_bfloat16 g_wql[INNER * DQ];
__device__ __nv_bfloat16 g_wkvh[2 * INNER * DC];
__device__ __nv_bfloat16 g_wkvl[2 * INNER * DC];
__device__ __nv_bfloat16 g_woh[DQ * INNER];
__device__ __nv_bfloat16 g_wol[DQ * INNER];

// ---------------------------------------------------------------------------
// PTX helpers
// ---------------------------------------------------------------------------
__device__ __forceinline__ uint32_t smem_u32(const void* p) {
    uint32_t a;
    asm("{ .reg .u64 t; cvta.to.shared.u64 t, %1; cvt.u32.u64 %0, t; }" : "=r"(a) : "l"(p));
    return a;
}
__device__ __forceinline__ void cpa16(uint32_t dst, const void* src) {
    asm volatile("cp.async.cg.shared.global [%0], [%1], 16;" :: "r"(dst), "l"(src));
}
__device__ __forceinline__ void cpa_commit() { asm volatile("cp.async.commit_group;" ::: "memory"); }
__device__ __forceinline__ void cpa_wait0()  { asm volatile("cp.async.wait_group 0;" ::: "memory"); }

__device__ __forceinline__ float ex2f(float x) {
    float y;
    asm("ex2.approx.f32 %0, %1;" : "=f"(y) : "f"(x));
    return y;
}

__device__ __forceinline__ void ldsm4(uint32_t* r, uint32_t addr) {
    asm volatile("ldmatrix.sync.aligned.m8n8.x4.shared.b16 {%0,%1,%2,%3}, [%4];"
                 : "=r"(r[0]), "=r"(r[1]), "=r"(r[2]), "=r"(r[3]) : "r"(addr));
}
__device__ __forceinline__ void ldsm4t(uint32_t* r, uint32_t addr) {
    asm volatile("ldmatrix.sync.aligned.m8n8.x4.trans.shared.b16 {%0,%1,%2,%3}, [%4];"
                 : "=r"(r[0]), "=r"(r[1]), "=r"(r[2]), "=r"(r[3]) : "r"(addr));
}
__device__ __forceinline__ void mma16816(float* c, const uint32_t* a, const uint32_t* b) {
    asm volatile(
        "mma.sync.aligned.m16n8k16.row.col.f32.bf16.bf16.f32 "
        "{%0,%1,%2,%3}, {%4,%5,%6,%7}, {%8,%9}, {%0,%1,%2,%3};"
        : "+f"(c[0]), "+f"(c[1]), "+f"(c[2]), "+f"(c[3])
        : "r"(a[0]), "r"(a[1]), "r"(a[2]), "r"(a[3]), "r"(b[0]), "r"(b[1]));
}

__device__ __forceinline__ uint32_t pack_bf16x2(float lo, float hi) {
    __nv_bfloat162 t = __floats2bfloat162_rn(lo, hi);
    return *reinterpret_cast<uint32_t*>(&t);
}
__device__ __forceinline__ uint32_t pack_residual(float lo, float hi, uint32_t hpack) {
    __nv_bfloat162 t = *reinterpret_cast<__nv_bfloat162*>(&hpack);
    return pack_bf16x2(lo - __low2float(t), hi - __high2float(t));
}

// ---------------------------------------------------------------------------
// Merged conversions (one launch, MLP=4 splits)
// ---------------------------------------------------------------------------
#define XSPLIT4 (MROWS * DQ / 4 / 1024)   // 2048
#define CSPLIT4 (MROWS * DC / 4 / 1024)   // 1536
#define SPLIT_BLOCKS (XSPLIT4 + CSPLIT4)  // 3584
#define CONV_BLOCKS  (SPLIT_BLOCKS + 1792)

__global__ void conv_all(const float* __restrict__ x, const float* __restrict__ ctx,
                         const float* __restrict__ Wq, const float* __restrict__ Wk,
                         const float* __restrict__ Wv, const float* __restrict__ Wo,
                         __nv_bfloat16* __restrict__ xh, __nv_bfloat16* __restrict__ xl,
                         __nv_bfloat16* __restrict__ ch, __nv_bfloat16* __restrict__ cl,
                         __nv_bfloat16* __restrict__ wqh, __nv_bfloat16* __restrict__ wql,
                         __nv_bfloat16* __restrict__ wkvh, __nv_bfloat16* __restrict__ wkvl,
                         __nv_bfloat16* __restrict__ woh, __nv_bfloat16* __restrict__ wol)
{
    int bid = blockIdx.x;
    if (bid < SPLIT_BLOCKS) {
        const float* A;
        __nv_bfloat16 *H, *L;
        int base;
        if (bid < XSPLIT4) { A = x; H = xh; L = xl; base = bid * 1024; }
        else { A = ctx; H = ch; L = cl; base = (bid - XSPLIT4) * 1024; }

        float4 v[4];
#pragma unroll
        for (int j = 0; j < 4; j++)
            v[j] = ((const float4*)A)[base + j * 256 + threadIdx.x];
#pragma unroll
        for (int j = 0; j < 4; j++) {
            const int i = base + j * 256 + threadIdx.x;
            float a[4] = {v[j].x, v[j].y, v[j].z, v[j].w};
            __nv_bfloat162 h2[2], l2[2];
#pragma unroll
            for (int k = 0; k < 2; k++) {
                __nv_bfloat16 h0 = __float2bfloat16_rn(a[2 * k]);
                __nv_bfloat16 h1 = __float2bfloat16_rn(a[2 * k + 1]);
                __nv_bfloat16 l0 = __float2bfloat16_rn(a[2 * k] - __bfloat162float(h0));
                __nv_bfloat16 l1 = __float2bfloat16_rn(a[2 * k + 1] - __bfloat162float(h1));
                h2[k] = __nv_bfloat162(h0, h1);
                l2[k] = __nv_bfloat162(l0, l1);
            }
            ((__nv_bfloat162*)H)[2 * i] = h2[0];
            ((__nv_bfloat162*)H)[2 * i + 1] = h2[1];
            ((__nv_bfloat162*)L)[2 * i] = l2[0];
            ((__nv_bfloat162*)L)[2 * i + 1] = l2[1];
        }
        return;
    }

    __shared__ float t[32][33];
    int wb = bid - SPLIT_BLOCKS;
    const float* W;
    __nv_bfloat16 *Th, *Tl;
    int K, N, loc, nx;
    if (wb < 512)       { W = Wq; Th = wqh; Tl = wql; K = DQ; N = INNER; loc = wb; nx = 16; }
    else if (wb < 896)  { W = Wk; Th = wkvh; Tl = wkvl; K = DC; N = INNER; loc = wb - 512; nx = 16; }
    else if (wb < 1280) { W = Wv; Th = wkvh + (size_t)INNER * DC; Tl = wkvl + (size_t)INNER * DC;
                          K = DC; N = INNER; loc = wb - 896; nx = 16; }
    else                { W = Wo; Th = woh; Tl = wol; K = INNER; N = DQ; loc = wb - 1280; nx = 32; }
    int n0 = (loc % nx) * 32, k0 = (loc / nx) * 32;
    int tx = threadIdx.x & 31, ty = threadIdx.x >> 5;
#pragma unroll
    for (int i = 0; i < 32; i += 8)
        t[ty + i][tx] = W[(size_t)(k0 + ty + i) * N + n0 + tx];
    __syncthreads();
#pragma unroll
    for (int i = 0; i < 32; i += 8) {
        float v = t[tx][ty + i];
        __nv_bfloat16 h = __float2bfloat16_rn(v);
        __nv_bfloat16 l = __float2bfloat16_rn(v - __bfloat162float(h));
        Th[(size_t)(n0 + ty + i) * K + k0 + tx] = h;
        Tl[(size_t)(n0 + ty + i) * K + k0 + tx] = l;
    }
}

// ---------------------------------------------------------------------------
// 2-pass split GEMM: pass1 loads (Ah,Bh,Bl) -> AhBh + AhBl;
//                    pass2 loads (Al,Bh)    -> AlBh.
// BK=64, pitch-72, 2-stage, SINGLE barrier per chunk:
//   loop: { cpa_wait0; __syncthreads(); issue(g+1); compute(g); }
// ---------------------------------------------------------------------------
#define GP 72
#define GT64 (128 * GP)
#define GEMM_DSMEM (2 * 3 * GT64 * 2)   // 110592 bytes

__device__ __forceinline__ void gemm2p_body(
    __nv_bfloat16* sm,   // [2][3][GT64]
    const __nv_bfloat16* Ah, const __nv_bfloat16* Al,
    const __nv_bfloat16* Bh, const __nv_bfloat16* Bl,
    const float* bias, float* Cf,
    __nv_bfloat16* Ch, __nv_bfloat16* Cl,
    __nv_bfloat16* Ch2, __nv_bfloat16* Cl2,
    int N, int K, int Nsplit, int m0, int n0, float cscale)
{
    const int tid = threadIdx.x;
    const int wid = tid >> 5;
    const int lane = tid & 31;
    const int wm = wid & 3;
    const int wn = wid >> 2;

    const int nkt = K >> 6;
    const int total = 2 * nkt;

    auto issue_chunk = [&](int g, int buf) {
        const bool p2 = g >= nkt;
        const int kt = p2 ? g - nkt : g;
        const int k0 = kt << 6;
        const __nv_bfloat16* As = p2 ? Al : Ah;
        __nv_bfloat16* base = sm + buf * 3 * GT64;
#pragma unroll
        for (int i = 0; i < 4; i++) {
            const int idx = tid + (i << 8);
            const int row = idx >> 3;
            const int col = (idx & 7) << 3;
            cpa16(smem_u32(base + row * GP + col),
                  As + (size_t)(m0 + row) * K + k0 + col);
            cpa16(smem_u32(base + GT64 + row * GP + col),
                  Bh + (size_t)(n0 + row) * K + k0 + col);
        }
        if (!p2) {
#pragma unroll
            for (int i = 0; i < 4; i++) {
                const int idx = tid + (i << 8);
                const int row = idx >> 3;
                const int col = (idx & 7) << 3;
                cpa16(smem_u32(base + 2 * GT64 + row * GP + col),
                      Bl + (size_t)(n0 + row) * K + k0 + col);
            }
        }
        cpa_commit();
    };

    float acc[2][8][4];
#pragma unroll
    for (int mi = 0; mi < 2; mi++)
#pragma unroll
        for (int nj = 0; nj < 8; nj++)
#pragma unroll
            for (int r = 0; r < 4; r++) acc[mi][nj][r] = 0.f;

    const int a_r = lane & 15;
    const int a_k = (lane >> 4) << 3;
    const int b_r = ((lane >> 4) << 3) + (lane & 7);
    const int b_k = ((lane >> 3) & 1) << 3;

    issue_chunk(0, 0);
#pragma unroll 1
    for (int g = 0; g < total; g++) {
        const int buf = g & 1;
        cpa_wait0();            // only group g in flight here
        __syncthreads();        // publish g's data + all warps done with buf g-1
        if (g + 1 < total) issue_chunk(g + 1, buf ^ 1);   // overwrites buf g-1: safe

        __nv_bfloat16* base = sm + buf * 3 * GT64;
        const bool p1 = g < nkt;
#pragma unroll
        for (int ks = 0; ks < 4; ks++) {
            uint32_t af[2][4], bfr[4][4];
            ldsm4(af[0], smem_u32(base + (wm * 32 + a_r) * GP + ks * 16 + a_k));
            ldsm4(af[1], smem_u32(base + (wm * 32 + 16 + a_r) * GP + ks * 16 + a_k));
#pragma unroll
            for (int ni = 0; ni < 4; ni++)
                ldsm4(bfr[ni], smem_u32(base + GT64 + (wn * 64 + ni * 16 + b_r) * GP + ks * 16 + b_k));
#pragma unroll
            for (int mi = 0; mi < 2; mi++)
#pragma unroll
                for (int nj = 0; nj < 8; nj++)
                    mma16816(acc[mi][nj], af[mi], &bfr[nj >> 1][(nj & 1) * 2]);
            if (p1) {
#pragma unroll
                for (int ni = 0; ni < 4; ni++)
                    ldsm4(bfr[ni], smem_u32(base + 2 * GT64 + (wn * 64 + ni * 16 + b_r) * GP + ks * 16 + b_k));
#pragma unroll
                for (int mi = 0; mi < 2; mi++)
#pragma unroll
                    for (int nj = 0; nj < 8; nj++)
                        mma16816(acc[mi][nj], af[mi], &bfr[nj >> 1][(nj & 1) * 2]);
            }
        }
    }

    const int er = lane >> 2;
    const int ec = (lane & 3) << 1;
#pragma unroll
    for (int mi = 0; mi < 2; mi++) {
        const int row = m0 + wm * 32 + mi * 16 + er;
#pragma unroll
        for (int nj = 0; nj < 8; nj++) {
            int col = n0 + wn * 64 + nj * 8 + ec;
            if (Cf) {
                float b0 = 0.f, b1 = 0.f;
                if (bias) { b0 = bias[col]; b1 = bias[col + 1]; }
                *(float2*)(Cf + (size_t)row * N + col) =
                    make_float2(acc[mi][nj][0] + b0, acc[mi][nj][1] + b1);
                *(float2*)(Cf + (size_t)(row + 8) * N + col) =
                    make_float2(acc[mi][nj][2] + b0, acc[mi][nj][3] + b1);
            } else {
                __nv_bfloat16* dh = Ch;
                __nv_bfloat16* dl = Cl;
                if (Ch2 && col >= Nsplit) { dh = Ch2; dl = Cl2; col -= Nsplit; }
                float a0 = acc[mi][nj][0] * cscale, a1 = acc[mi][nj][1] * cscale;
                float a2 = acc[mi][nj][2] * cscale, a3 = acc[mi][nj][3] * cscale;
                uint32_t h0 = pack_bf16x2(a0, a1);
                uint32_t l0 = pack_residual(a0, a1, h0);
                uint32_t h1 = pack_bf16x2(a2, a3);
                uint32_t l1 = pack_residual(a2, a3, h1);
                *(uint32_t*)(dh + (size_t)row * Nsplit + col) = h0;
                *(uint32_t*)(dl + (size_t)row * Nsplit + col) = l0;
                *(uint32_t*)(dh + (size_t)(row + 8) * Nsplit + col) = h1;
                *(uint32_t*)(dl + (size_t)(row + 8) * Nsplit + col) = l1;
            }
        }
    }
}

// Merged Q + KV projections (Q outputs pre-scaled by SCL2E)
__global__ __launch_bounds__(256, 2) void proj_qkv_kernel(
    const __nv_bfloat16* __restrict__ xh, const __nv_bfloat16* __restrict__ xl,
    const __nv_bfloat16* __restrict__ wqh, const __nv_bfloat16* __restrict__ wql,
    const __nv_bfloat16* __restrict__ ch, const __nv_bfloat16* __restrict__ cl,
    const __nv_bfloat16* __restrict__ wkvh, const __nv_bfloat16* __restrict__ wkvl,
    __nv_bfloat16* __restrict__ qh, __nv_bfloat16* __restrict__ ql,
    __nv_bfloat16* __restrict__ kh, __nv_bfloat16* __restrict__ kl,
    __nv_bfloat16* __restrict__ vh, __nv_bfloat16* __restrict__ vl)
{
    extern __shared__ __nv_bfloat16 gsm[];
    const int bid = blockIdx.x;
    if (bid < 256) {
        gemm2p_body(gsm, xh, xl, wqh, wql, nullptr, nullptr,
                    qh, ql, nullptr, nullptr,
                    INNER, DQ, INNER, (bid >> 2) * 128, (bid & 3) * 128, SCL2E);
    } else {
        const int r = bid - 256;
        gemm2p_body(gsm, ch, cl, wkvh, wkvl, nullptr, nullptr,
                    kh, kl, vh, vl,
                    2 * INNER, DC, INNER, (r >> 3) * 128, (r & 7) * 128, 1.0f);
    }
}

// Output projection (fp32 + bias)
__global__ __launch_bounds__(256, 2) void out_proj_kernel(
    const __nv_bfloat16* __restrict__ aoh, const __nv_bfloat16* __restrict__ aol,
    const __nv_bfloat16* __restrict__ woh, const __nv_bfloat16* __restrict__ wol,
    const float* __restrict__ bias, float* __restrict__ out)
{
    extern __shared__ __nv_bfloat16 gsm[];
    gemm2p_body(gsm, aoh, aol, woh, wol, bias, out,
                nullptr, nullptr, nullptr, nullptr,
                DQ, INNER, DQ, (int)blockIdx.y * 128, (int)blockIdx.x * 128, 1.0f);
}

// ---------------------------------------------------------------------------
// Tensor-core flash attention — single barrier per KV tile.
// ---------------------------------------------------------------------------
#define FPITCH 72
#define KVT    (64 * FPITCH)
#define FLASH_SMEM ((2 * 128 * FPITCH + 2 * 4 * KVT) * 2)   // 110592 bytes

__global__ __launch_bounds__(256, 2) void flash_mma_kernel(
    const __nv_bfloat16* __restrict__ Qh_, const __nv_bfloat16* __restrict__ Ql_,
    const __nv_bfloat16* __restrict__ Kh_, const __nv_bfloat16* __restrict__ Kl_,
    const __nv_bfloat16* __restrict__ Vh_, const __nv_bfloat16* __restrict__ Vl_,
    __nv_bfloat16* __restrict__ AOh, __nv_bfloat16* __restrict__ AOl)
{
    extern __shared__ char fsmc[];
    __nv_bfloat16* fsm = (__nv_bfloat16*)fsmc;
    __nv_bfloat16* sQh = fsm;
    __nv_bfloat16* sQl = sQh + 128 * FPITCH;
    __nv_bfloat16* sKV = sQl + 128 * FPITCH;

    const int tid = threadIdx.x;
    const int wid = tid >> 5;
    const int lane = tid & 31;
    const int qt = blockIdx.x, h = blockIdx.y, b = blockIdx.z;
    const size_t qrow0 = (size_t)b * NQ + (size_t)qt * 128;
    const size_t krow0 = (size_t)b * NC;
    const int colbase = h * DIMH;

    auto issue_kv = [&](int t, int buf) {
        __nv_bfloat16* base = sKV + buf * 4 * KVT;
        const size_t gr = (krow0 + t * 64) * INNER + colbase;
#pragma unroll
        for (int i = 0; i < 2; i++) {
            const int idx = tid + (i << 8);
            const int r = idx >> 3;
            const int c = (idx & 7) << 3;
            const size_t go = gr + (size_t)r * INNER + c;
            const uint32_t so = smem_u32(base + r * FPITCH + c);
            cpa16(so + 0 * KVT * 2, Kh_ + go);
            cpa16(so + 1 * KVT * 2, Kl_ + go);
            cpa16(so + 2 * KVT * 2, Vh_ + go);
            cpa16(so + 3 * KVT * 2, Vl_ + go);
        }
        cpa_commit();
    };

#pragma unroll
    for (int i = 0; i < 4; i++) {
        const int idx = tid + (i << 8);
        const int r = idx >> 3;
        const int c = (idx & 7) << 3;
        const size_t go = (qrow0 + r) * INNER + colbase + c;
        cpa16(smem_u32(sQh + r * FPITCH + c), Qh_ + go);
        cpa16(smem_u32(sQl + r * FPITCH + c), Ql_ + go);
    }
    issue_kv(0, 0);

    const int a_r = lane & 15;
    const int a_k = (lane >> 4) << 3;
    const int b_r = ((lane >> 4) << 3) + (lane & 7);
    const int b_k = ((lane >> 3) & 1) << 3;
    const int v_r = (((lane >> 3) & 1) << 3) + (lane & 7);
    const int v_c = (lane >> 4) << 3;
    const int wq = wid * 16;

    float acc[8][4];
#pragma unroll
    for (int j = 0; j < 8; j++)
#pragma unroll
        for (int r = 0; r < 4; r++) acc[j][r] = 0.f;
    float m0 = -INFINITY, m1 = -INFINITY, l0 = 0.f, l1 = 0.f;

    const int NT = NC / 64;
#pragma unroll 1
    for (int t = 0; t < NT; t++) {
        const int buf = t & 1;
        cpa_wait0();            // only tile t (and Q on t=0) in flight
        __syncthreads();        // publish + all warps done with buf t-1
        if (t + 1 < NT) issue_kv(t + 1, buf ^ 1);

        __nv_bfloat16* kh = sKV + buf * 4 * KVT;
        __nv_bfloat16* kl = kh + KVT;
        __nv_bfloat16* vh = kh + 2 * KVT;
        __nv_bfloat16* vl = kh + 3 * KVT;

        float s[8][4];
#pragma unroll
        for (int j = 0; j < 8; j++)
#pragma unroll
            for (int r = 0; r < 4; r++) s[j][r] = 0.f;

#pragma unroll
        for (int kc = 0; kc < 4; kc++) {
            uint32_t aq[4], aql[4], bk[4][4];
            ldsm4(aq, smem_u32(&sQh[(wq + a_r) * FPITCH + kc * 16 + a_k]));
            ldsm4(aql, smem_u32(&sQl[(wq + a_r) * FPITCH + kc * 16 + a_k]));
#pragma unroll
            for (int nb = 0; nb < 4; nb++)
                ldsm4(bk[nb], smem_u32(&kh[(nb * 16 + b_r) * FPITCH + kc * 16 + b_k]));
#pragma unroll
            for (int j = 0; j < 8; j++) mma16816(s[j], aq, &bk[j >> 1][(j & 1) * 2]);
#pragma unroll
            for (int j = 0; j < 8; j++) mma16816(s[j], aql, &bk[j >> 1][(j & 1) * 2]);
#pragma unroll
            for (int nb = 0; nb < 4; nb++)
                ldsm4(bk[nb], smem_u32(&kl[(nb * 16 + b_r) * FPITCH + kc * 16 + b_k]));
#pragma unroll
            for (int j = 0; j < 8; j++) mma16816(s[j], aq, &bk[j >> 1][(j & 1) * 2]);
        }

        float mx0 = -INFINITY, mx1 = -INFINITY;
#pragma unroll
        for (int j = 0; j < 8; j++) {
            mx0 = fmaxf(mx0, fmaxf(s[j][0], s[j][1]));
            mx1 = fmaxf(mx1, fmaxf(s[j][2], s[j][3]));
        }
        mx0 = fmaxf(mx0, __shfl_xor_sync(0xffffffffu, mx0, 1));
        mx0 = fmaxf(mx0, __shfl_xor_sync(0xffffffffu, mx0, 2));
        mx1 = fmaxf(mx1, __shfl_xor_sync(0xffffffffu, mx1, 1));
        mx1 = fmaxf(mx1, __shfl_xor_sync(0xffffffffu, mx1, 2));
        const float mn0 = fmaxf(m0, mx0);
        const float mn1 = fmaxf(m1, mx1);
        const float al0 = ex2f(m0 - mn0);
        const float al1 = ex2f(m1 - mn1);
        m0 = mn0; m1 = mn1;

        float ps0 = 0.f, ps1 = 0.f;
        uint32_t ph[8][2];
#pragma unroll
        for (int j = 0; j < 8; j++) {
            s[j][0] = ex2f(s[j][0] - mn0);
            s[j][1] = ex2f(s[j][1] - mn0);
            s[j][2] = ex2f(s[j][2] - mn1);
            s[j][3] = ex2f(s[j][3] - mn1);
            ps0 += s[j][0] + s[j][1];
            ps1 += s[j][2] + s[j][3];
            ph[j][0] = pack_bf16x2(s[j][0], s[j][1]);
            ph[j][1] = pack_bf16x2(s[j][2], s[j][3]);
        }
        l0 = l0 * al0 + ps0;
        l1 = l1 * al1 + ps1;
#pragma unroll
        for (int j = 0; j < 8; j++) {
            acc[j][0] *= al0; acc[j][1] *= al0;
            acc[j][2] *= al1; acc[j][3] *= al1;
        }

#pragma unroll
        for (int kc = 0; kc < 4; kc++) {
            uint32_t ap[4] = {ph[2 * kc][0], ph[2 * kc][1], ph[2 * kc + 1][0], ph[2 * kc + 1][1]};
            uint32_t apl[4];
            apl[0] = pack_residual(s[2 * kc][0], s[2 * kc][1], ph[2 * kc][0]);
            apl[1] = pack_residual(s[2 * kc][2], s[2 * kc][3], ph[2 * kc][1]);
            apl[2] = pack_residual(s[2 * kc + 1][0], s[2 * kc + 1][1], ph[2 * kc + 1][0]);
            apl[3] = pack_residual(s[2 * kc + 1][2], s[2 * kc + 1][3], ph[2 * kc + 1][1]);
            uint32_t bv[4][4];
#pragma unroll
            for (int nb = 0; nb < 4; nb++)
                ldsm4t(bv[nb], smem_u32(&vh[(kc * 16 + v_r) * FPITCH + nb * 16 + v_c]));
#pragma unroll
            for (int j = 0; j < 8; j++) mma16816(acc[j], ap, &bv[j >> 1][(j & 1) * 2]);
#pragma unroll
            for (int j = 0; j < 8; j++) mma16816(acc[j], apl, &bv[j >> 1][(j & 1) * 2]);
#pragma unroll
            for (int nb = 0; nb < 4; nb++)
                ldsm4t(bv[nb], smem_u32(&vl[(kc * 16 + v_r) * FPITCH + nb * 16 + v_c]));
#pragma unroll
            for (int j = 0; j < 8; j++) mma16816(acc[j], ap, &bv[j >> 1][(j & 1) * 2]);
        }
    }

    l0 += __shfl_xor_sync(0xffffffffu, l0, 1);
    l0 += __shfl_xor_sync(0xffffffffu, l0, 2);
    l1 += __shfl_xor_sync(0xffffffffu, l1, 1);
    l1 += __shfl_xor_sync(0xffffffffu, l1, 2);
    const float inv0 = 1.f / l0;
    const float inv1 = 1.f / l1;
    const size_t row0 = qrow0 + wq + (lane >> 2);
    const size_t row1 = row0 + 8;
#pragma unroll
    for (int j = 0; j < 8; j++) {
        const int col = colbase + j * 8 + (lane & 3) * 2;
        float v0 = acc[j][0] * inv0, v1 = acc[j][1] * inv0;
        uint32_t hp = pack_bf16x2(v0, v1);
        *(uint32_t*)(AOh + row0 * INNER + col) = hp;
        *(uint32_t*)(AOl + row0 * INNER + col) = pack_residual(v0, v1, hp);
        float v2 = acc[j][2] * inv1, v3 = acc[j][3] * inv1;
        uint32_t hp1 = pack_bf16x2(v2, v3);
        *(uint32_t*)(AOh + row1 * INNER + col) = hp1;
        *(uint32_t*)(AOl + row1 * INNER + col) = pack_residual(v2, v3, hp1);
    }
}

// ---------------------------------------------------------------------------
extern "C" void kernel_launch(void* const* d_in, const int* in_sizes, int n_in,
                              void* d_out, int out_size)
{
    const float* x   = (const float*)d_in[0];
    const float* ctx = (const float*)d_in[1];
    const float* Wq  = (const float*)d_in[2];
    const float* Wk  = (const float*)d_in[3];
    const float* Wv  = (const float*)d_in[4];
    const float* Wo  = (const float*)d_in[5];
    const float* bo  = (const float*)d_in[6];
    float* out = (float*)d_out;

    __nv_bfloat16 *xh, *xl, *ch, *cl;
    __nv_bfloat16 *qh, *ql, *kh, *kl, *vh, *vl, *aoh, *aol;
    __nv_bfloat16 *wqh, *wql, *wkvh, *wkvl, *woh, *wol;
    cudaGetSymbolAddress((void**)&xh, g_xh);   cudaGetSymbolAddress((void**)&xl, g_xl);
    cudaGetSymbolAddress((void**)&ch, g_ch);   cudaGetSymbolAddress((void**)&cl, g_cl);
    cudaGetSymbolAddress((void**)&qh, g_qh);   cudaGetSymbolAddress((void**)&ql, g_ql);
    cudaGetSymbolAddress((void**)&kh, g_kh);   cudaGetSymbolAddress((void**)&kl, g_kl);
    cudaGetSymbolAddress((void**)&vh, g_vh);   cudaGetSymbolAddress((void**)&vl, g_vl);
    cudaGetSymbolAddress((void**)&aoh, g_aoh); cudaGetSymbolAddress((void**)&aol, g_aol);
    cudaGetSymbolAddress((void**)&wqh, g_wqh); cudaGetSymbolAddress((void**)&wql, g_wql);
    cudaGetSymbolAddress((void**)&wkvh, g_wkvh); cudaGetSymbolAddress((void**)&wkvl, g_wkvl);
    cudaGetSymbolAddress((void**)&woh, g_woh); cudaGetSymbolAddress((void**)&wol, g_wol);

    // ---- conversions ----
    conv_all<<<CONV_BLOCKS, 256>>>(x, ctx, Wq, Wk, Wv, Wo,
                                   xh, xl, ch, cl, wqh, wql, wkvh, wkvl, woh, wol);

    // ---- Q + KV projections (2-pass, BK=64, single-barrier) ----
    cudaFuncSetAttribute(proj_qkv_kernel, cudaFuncAttributeMaxDynamicSharedMemorySize,
                         GEMM_DSMEM);
    proj_qkv_kernel<<<768, 256, GEMM_DSMEM>>>(xh, xl, wqh, wql, ch, cl, wkvh, wkvl,
                                              qh, ql, kh, kl, vh, vl);

    // ---- flash attention (single-barrier) ----
    cudaFuncSetAttribute(flash_mma_kernel, cudaFuncAttributeMaxDynamicSharedMemorySize,
                         FLASH_SMEM);
    flash_mma_kernel<<<dim3(NQ / 128, NHEADS, BATCH), 256, FLASH_SMEM>>>(
        qh, ql, kh, kl, vh, vl, aoh, aol);

    // ---- output projection (2-pass, BK=64, single-barrier) ----
    cudaFuncSetAttribute(out_proj_kernel, cudaFuncAttributeMaxDynamicSharedMemorySize,
                         GEMM_DSMEM);
    out_proj_kernel<<<dim3(DQ / 128, MROWS / 128), 256, GEMM_DSMEM>>>(
        aoh, aol, woh, wol, bo, out);
}